// round 7
// baseline (speedup 1.0000x reference)
#include <cuda_runtime.h>
#include <cstdint>
#include <cstddef>

#define NFEAT 17
#define HDIM 8
#define BSZ 256
#define TSTEPS 512
#define XDIM 59
#define CHK 32
#define NCHK (TSTEPS/CHK)
#define BPC 2
#define NTHREADS 288
#define ROWF 80                      // padded floats per (bl,tl) row
#define PLANEF (CHK*ROWF + 8)        // +8 floats: bank-shift between batch planes

typedef unsigned long long u64;

// slot = warp*4 + group. Heavy warps d-homogeneous: w1={f3,f3,f2,f2}, w2={f4,f4,f1,f1}.
__device__ __constant__ int8_t c_slot_f[36] = {
   6, 6, 7, 7,   3, 3, 2, 2,   4, 4, 1, 1,   0, 0, 5, 5,
   8, 8, 9, 9,  10,10,11,11,  12,12,13,13,  14,14,15,15,  16,16,16,16};
__device__ __constant__ int8_t c_slot_b[36] = {
   0, 1, 0, 1,   0, 1, 0, 1,   0, 1, 0, 1,   0, 1, 0, 1,
   0, 1, 0, 1,   0, 1, 0, 1,   0, 1, 0, 1,   0, 1, 0, 1,   0, 1, 0, 1};
__device__ __constant__ int8_t c_slot_wr[36] = {
   1, 1, 1, 1,   1, 1, 1, 1,   1, 1, 1, 1,   1, 1, 1, 1,
   1, 1, 1, 1,   1, 1, 1, 1,   1, 1, 1, 1,   1, 1, 1, 1,   1, 1, 0, 0};
// dim-PAIRS per warp (warp-uniform gx bound)
__device__ __constant__ int8_t c_warp_dp[9] = {1,7,6,1,1,1,1,1,1};
// feature -> float offset of its slot within a padded row
__device__ __constant__ int16_t c_foff[17] =
  {52,40,16,0,28, 54,56,58,60,62,64,66,68,70,72,74,76};
// source column s (0..58) -> dst float offset within padded row
__device__ __constant__ int16_t c_dst[59] = {
  52,53,                                        // f0 (d=2)
  40,41,42,43,44,45,46,47,                      // f1 (d=8; pads 48..51 zero)
  16,17,18,19,20,21,22,23,24,25,26,27,          // f2 (d=12)
   0, 1, 2, 3, 4, 5, 6, 7, 8, 9,10,11,12,       // f3 (d=13; pads 13..15 zero)
  28,29,30,31,32,33,34,35,36,37,38,39,          // f4 (d=12)
  54,56,58,60,62,64,66,68,70,72,74,76};         // f5..f16 (d=1; odd floats zero)

template<int N> struct IC { static constexpr int value = N; };

__device__ __forceinline__ float tanh_ap(float x){
  float y; asm("tanh.approx.f32 %0, %1;" : "=f"(y) : "f"(x)); return y;
}
__device__ __forceinline__ u64 pk(float lo, float hi){
  u64 r; asm("mov.b64 %0,{%1,%2};" : "=l"(r) : "f"(lo), "f"(hi)); return r;
}
__device__ __forceinline__ void upk(float& lo, float& hi, u64 p){
  asm("mov.b64 {%0,%1},%2;" : "=f"(lo), "=f"(hi) : "l"(p));
}
__device__ __forceinline__ u64 fma2(u64 a, u64 b, u64 c){
  u64 d; asm("fma.rn.f32x2 %0,%1,%2,%3;" : "=l"(d) : "l"(a), "l"(b), "l"(c)); return d;
}
__device__ __forceinline__ u64 add2(u64 a, u64 b){
  u64 d; asm("add.rn.f32x2 %0,%1,%2;" : "=l"(d) : "l"(a), "l"(b)); return d;
}
__device__ __forceinline__ float hsum(u64 p){
  float lo, hi; upk(lo, hi, p); return lo + hi;
}
__device__ __forceinline__ u64 asu(double d){ return __double_as_longlong(d); }

extern "C" __global__ void __launch_bounds__(NTHREADS, 1)
mcgru_kernel(const float* __restrict__ x,   const float* __restrict__ Wih,
             const float* __restrict__ Whh, const float* __restrict__ bih,
             const float* __restrict__ bhh, float* __restrict__ out)
{
  __shared__ __align__(16) float xs[2][BPC][PLANEF];      // ~41 KB

  const int tid  = threadIdx.x;
  const int w    = tid >> 5;
  const int slot = tid >> 3;
  const int j    = tid & 7;
  const int f    = c_slot_f[slot];
  const int bl   = c_slot_b[slot];
  const bool wen = (bool)c_slot_wr[slot];
  const int dp   = c_warp_dp[w];
  const int foff = c_foff[f];
  const int bg0  = blockIdx.x * BPC;

  // ---- zero x buffers once (pads must be zero; staging writes data only)
  {
    float4 z = make_float4(0.f,0.f,0.f,0.f);
    float4* p4 = (float4*)&xs[0][0][0];
    for (int i = tid; i < (int)(sizeof(xs)/16); i += NTHREADS) p4[i] = z;
  }

  // ---- weights in registers, dim-paired u64 for fma.rn.f32x2.
  // r/z pre-scaled 0.5 (sigmoid(x)=.5+.5*tanh(x/2)); hh n-path pre-scaled 0.5.
  u64 wrp[7], wzp[7], wnp[7];
  {
    const float* Wf = Wih + f*24*13;
    #pragma unroll
    for (int p = 0; p < 7; ++p){
      int d0 = 2*p, d1 = 2*p + 1;
      float r0 = Wf[(0 + j)*13 + d0], z0 = Wf[(8 + j)*13 + d0], n0 = Wf[(16 + j)*13 + d0];
      float r1 = 0.f, z1 = 0.f, n1 = 0.f;
      if (d1 < 13){ r1 = Wf[(0 + j)*13 + d1]; z1 = Wf[(8 + j)*13 + d1]; n1 = Wf[(16 + j)*13 + d1]; }
      wrp[p] = pk(0.5f*r0, 0.5f*r1);
      wzp[p] = pk(0.5f*z0, 0.5f*z1);
      wnp[p] = pk(n0, n1);
    }
  }
  u64 urp[4], uzp[4], unp[4];
  {
    const float* Uf = Whh + f*24*8;
    #pragma unroll
    for (int p = 0; p < 4; ++p){
      urp[p] = pk(0.5f*Uf[(0 + j)*8 + 2*p], 0.5f*Uf[(0 + j)*8 + 2*p+1]);
      uzp[p] = pk(0.5f*Uf[(8 + j)*8 + 2*p], 0.5f*Uf[(8 + j)*8 + 2*p+1]);
      unp[p] = pk(0.5f*Uf[(16 + j)*8 + 2*p], 0.5f*Uf[(16 + j)*8 + 2*p+1]);
    }
  }
  const u64 brp  = pk(0.5f*(bih[f*24 + j]     + bhh[f*24 + j]),     0.f);
  const u64 bzp  = pk(0.5f*(bih[f*24 + 8 + j] + bhh[f*24 + 8 + j]), 0.f);
  const u64 bxnp = pk(bih[f*24 + 16 + j], 0.f);
  const u64 bhnp = pk(0.5f*bhh[f*24 + 16 + j], 0.f);
  const u64 Z64  = 0ULL;

  // ---- staging: 4 threads per (bl,tl) row, 15 cols each, 4B cp.async into
  // the padded per-feature layout.
  auto stage = [&](int c, int buf){
    int r = tid >> 2;
    if (r < BPC*CHK){
      int sbl = r >> 5, stl = r & (CHK-1);
      const float* src = x + ((size_t)(bg0 + sbl)*TSTEPS + (size_t)c*CHK + stl)*XDIM;
      float* drow = &xs[buf][sbl][0] + stl*ROWF;
      int c0 = (tid & 3) * 15;
      #pragma unroll
      for (int k = 0; k < 15; ++k){
        int s = c0 + k;
        if (s < XDIM){
          uint32_t d = (uint32_t)__cvta_generic_to_shared(drow + c_dst[s]);
          asm volatile("cp.async.ca.shared.global [%0], [%1], 4;" :: "r"(d), "l"(src + s) : "memory");
        }
      }
    }
  };

  stage(0, 0); asm volatile("cp.async.commit_group;" ::: "memory");
  stage(1, 1); asm volatile("cp.async.commit_group;" ::: "memory");

  float h = 0.f;
  float* outp = out + (((size_t)(bg0 + bl)*TSTEPS)*NFEAT + f)*HDIM + j;

  // One chunk: 4-step sub-blocks. Phase 1 computes gx for 4 steps (independent
  // of h — dense issue, hides LDS). Phase 2 runs the serial recurrence.
  auto run_chunk = [&](auto DPc, const float* xbase, float* outc){
    constexpr int DP = decltype(DPc)::value;
    for (int tb = 0; tb < CHK; tb += 4){
      u64 GR[4], GZ[4], GN[4];
      #pragma unroll
      for (int u = 0; u < 4; ++u){
        const float* xp = xbase + (tb + u)*ROWF;
        u64 X[7];
        if constexpr (DP == 1){
          X[0] = asu(*(const double*)xp);
        } else {
          const double2* xq = (const double2*)xp;
          #pragma unroll
          for (int q = 0; q < DP/2; ++q){
            double2 v = xq[q];
            X[2*q] = asu(v.x); X[2*q+1] = asu(v.y);
          }
          if constexpr (DP & 1){ X[DP-1] = asu(((const double*)xp)[DP-1]); }
        }
        u64 gr = brp, gz = bzp, gn = bxnp;
        #pragma unroll
        for (int p = 0; p < DP; ++p){
          gr = fma2(wrp[p], X[p], gr);
          gz = fma2(wzp[p], X[p], gz);
          gn = fma2(wnp[p], X[p], gn);
        }
        GR[u] = gr; GZ[u] = gz; GN[u] = gn;
      }
      #pragma unroll
      for (int u = 0; u < 4; ++u){
        float hk0 = __shfl_sync(0xFFFFFFFFu, h, 0, 8);
        float hk1 = __shfl_sync(0xFFFFFFFFu, h, 1, 8);
        float hk2 = __shfl_sync(0xFFFFFFFFu, h, 2, 8);
        float hk3 = __shfl_sync(0xFFFFFFFFu, h, 3, 8);
        float hk4 = __shfl_sync(0xFFFFFFFFu, h, 4, 8);
        float hk5 = __shfl_sync(0xFFFFFFFFu, h, 5, 8);
        float hk6 = __shfl_sync(0xFFFFFFFFu, h, 6, 8);
        float hk7 = __shfl_sync(0xFFFFFFFFu, h, 7, 8);
        u64 H0 = pk(hk0, hk1), H1 = pk(hk2, hk3), H2 = pk(hk4, hk5), H3 = pk(hk6, hk7);

        u64 rA = fma2(urp[0], H0, GR[u]); rA = fma2(urp[1], H1, rA);
        u64 rB = fma2(urp[2], H2, Z64);   rB = fma2(urp[3], H3, rB);
        float tr = tanh_ap(hsum(add2(rA, rB)));

        u64 zA = fma2(uzp[0], H0, GZ[u]); zA = fma2(uzp[1], H1, zA);
        u64 zB = fma2(uzp[2], H2, Z64);   zB = fma2(uzp[3], H3, zB);
        float tz = tanh_ap(hsum(add2(zA, zB)));

        u64 nA = fma2(unp[0], H0, bhnp);  nA = fma2(unp[1], H1, nA);
        u64 nB = fma2(unp[2], H2, Z64);   nB = fma2(unp[3], H3, nB);
        u64 hnp = add2(nA, nB);
        float hnh = hsum(hnp);                 // 0.5*(Un h + bhn)
        float s   = hsum(add2(GN[u], hnp));    // gn + hnh
        float a   = fmaf(tr, hnh, s);          // gn + r*(Un h + bhn)
        float n   = tanh_ap(a);
        float uu  = 0.5f*(h - n);
        h = fmaf(tz, uu, n + uu);              // (1-z)*n + z*h
        if (wen) outc[(size_t)(tb + u)*(NFEAT*HDIM)] = h;
      }
    }
  };

  for (int c = 0; c < NCHK; ++c){
    asm volatile("cp.async.wait_group 1;" ::: "memory");
    __syncthreads();
    const float* xbase = &xs[c & 1][bl][0] + foff;
    float* outc = outp + (size_t)c*CHK*(NFEAT*HDIM);

    if (dp == 7)      run_chunk(IC<7>{}, xbase, outc);
    else if (dp == 6) run_chunk(IC<6>{}, xbase, outc);
    else              run_chunk(IC<1>{}, xbase, outc);

    __syncthreads();                           // buffer free before restage
    if (c + 2 < NCHK) stage(c + 2, c & 1);
    asm volatile("cp.async.commit_group;" ::: "memory");
  }
}

extern "C" void kernel_launch(void* const* d_in, const int* in_sizes, int n_in,
                              void* d_out, int out_size)
{
  const float* x   = (const float*)d_in[0];
  const float* Wih = (const float*)d_in[1];
  const float* Whh = (const float*)d_in[2];
  const float* bih = (const float*)d_in[3];
  const float* bhh = (const float*)d_in[4];
  (void)in_sizes; (void)n_in; (void)out_size;
  mcgru_kernel<<<BSZ/BPC, NTHREADS>>>(x, Wih, Whh, bih, bhh, (float*)d_out);
}

// round 8
// speedup vs baseline: 1.1718x; 1.1718x over previous
#include <cuda_runtime.h>
#include <cstdint>
#include <cstddef>

#define NFEAT 17
#define HDIM 8
#define BSZ 256
#define TSTEPS 512
#define XDIM 59
#define CHK 32
#define NCHK (TSTEPS/CHK)
#define BPC 2
#define NTHREADS 288
#define ROWPAD (CHK*XDIM + 16)   // contiguous chunk + zeroed pad for pair overread

typedef unsigned long long u64;

// slot = warp*4 + group. Heavy warps: w1={f3,f3,f2,f2}, w2={f4,f4,f1,f1}.
// SMSP0 (w0,w4,w8) carries only d<=1 features.
__device__ __constant__ int8_t c_slot_f[36] = {
   6, 6, 7, 7,   3, 3, 2, 2,   4, 4, 1, 1,   0, 0, 5, 5,
   8, 8, 9, 9,  10,10,11,11,  12,12,13,13,  14,14,15,15,  16,16,16,16};
__device__ __constant__ int8_t c_slot_b[36] = {
   0, 1, 0, 1,   0, 1, 0, 1,   0, 1, 0, 1,   0, 1, 0, 1,
   0, 1, 0, 1,   0, 1, 0, 1,   0, 1, 0, 1,   0, 1, 0, 1,   0, 1, 0, 1};
__device__ __constant__ int8_t c_slot_wr[36] = {
   1, 1, 1, 1,   1, 1, 1, 1,   1, 1, 1, 1,   1, 1, 1, 1,
   1, 1, 1, 1,   1, 1, 1, 1,   1, 1, 1, 1,   1, 1, 1, 1,   1, 1, 0, 0};
// dim-PAIR count per warp (warp-uniform gx bound; extra pairs have zero weights)
__device__ __constant__ int8_t c_warp_dp[9] = {1,7,7,2,1,1,1,1,1};
// segment start offsets (cumsum of DIMS)
__device__ __constant__ int8_t c_start[17] =
  {0,2,10,22,35,47,48,49,50,51,52,53,54,55,56,57,58};

template<int N> struct IC { static constexpr int value = N; };

__device__ __forceinline__ void cp16(uint32_t s, const float* g){
  asm volatile("cp.async.ca.shared.global [%0], [%1], 16;" :: "r"(s), "l"(g) : "memory");
}
__device__ __forceinline__ float tanh_ap(float x){
  float y; asm("tanh.approx.f32 %0, %1;" : "=f"(y) : "f"(x)); return y;
}
__device__ __forceinline__ u64 pk(float lo, float hi){
  u64 r; asm("mov.b64 %0,{%1,%2};" : "=l"(r) : "f"(lo), "f"(hi)); return r;
}
__device__ __forceinline__ void upk(float& lo, float& hi, u64 p){
  asm("mov.b64 {%0,%1},%2;" : "=f"(lo), "=f"(hi) : "l"(p));
}
__device__ __forceinline__ u64 fma2(u64 a, u64 b, u64 c){
  u64 d; asm("fma.rn.f32x2 %0,%1,%2,%3;" : "=l"(d) : "l"(a), "l"(b), "l"(c)); return d;
}
__device__ __forceinline__ u64 add2(u64 a, u64 b){
  u64 d; asm("add.rn.f32x2 %0,%1,%2;" : "=l"(d) : "l"(a), "l"(b)); return d;
}
__device__ __forceinline__ float hsum(u64 p){
  float lo, hi; upk(lo, hi, p); return lo + hi;
}
__device__ __forceinline__ u64 asu(double d){ return __double_as_longlong(d); }

extern "C" __global__ void __launch_bounds__(NTHREADS, 1)
mcgru_kernel(const float* __restrict__ x,   const float* __restrict__ Wih,
             const float* __restrict__ Whh, const float* __restrict__ bih,
             const float* __restrict__ bhh, float* __restrict__ out)
{
  __shared__ __align__(16) float xs[2][BPC][ROWPAD];   // 30.5 KB, R4 layout

  const int tid  = threadIdx.x;
  const int w    = tid >> 5;
  const int slot = tid >> 3;
  const int j    = tid & 7;
  const int f    = c_slot_f[slot];
  const int bl   = c_slot_b[slot];
  const bool wen = (bool)c_slot_wr[slot];
  const int dp   = c_warp_dp[w];
  const int startf = c_start[f];
  const int p0   = startf & 1;
  const int bg0  = blockIdx.x * BPC;

  // zero the overread pads once (data region overwritten by staging anyway)
  for (int i = tid; i < 16; i += NTHREADS){
    xs[0][0][CHK*XDIM + i] = 0.f; xs[0][1][CHK*XDIM + i] = 0.f;
    xs[1][0][CHK*XDIM + i] = 0.f; xs[1][1][CHK*XDIM + i] = 0.f;
  }

  // ---- dual-parity weight pair sets.
  // Step tl reads pairs from even base = startf + 59*tl - par, par=(p0+tl)&1.
  // wE used on even tl, wO on odd tl; each is aligned-or-shifted per p0.
  // r/z pre-scaled 0.5 (sigmoid(x)=.5+.5*tanh(x/2)).
  u64 wEr[7], wEz[7], wEn[7], wOr[7], wOz[7], wOn[7];
  {
    const float* Wf = Wih + f*24*13;
    auto wat = [&](int row, int d)->float {
      return (d >= 0 && d < 13) ? Wf[row*13 + d] : 0.f;   // Wih zero-masked past true d
    };
    #pragma unroll
    for (int p = 0; p < 7; ++p){
      int a0 = 2*p, a1 = 2*p+1, s0 = 2*p-1, s1 = 2*p;
      u64 rA = pk(0.5f*wat(0+j,a0),  0.5f*wat(0+j,a1));
      u64 rS = pk(0.5f*wat(0+j,s0),  0.5f*wat(0+j,s1));
      u64 zA = pk(0.5f*wat(8+j,a0),  0.5f*wat(8+j,a1));
      u64 zS = pk(0.5f*wat(8+j,s0),  0.5f*wat(8+j,s1));
      u64 nA = pk(wat(16+j,a0), wat(16+j,a1));
      u64 nS = pk(wat(16+j,s0), wat(16+j,s1));
      wEr[p] = p0 ? rS : rA;  wOr[p] = p0 ? rA : rS;
      wEz[p] = p0 ? zS : zA;  wOz[p] = p0 ? zA : zS;
      wEn[p] = p0 ? nS : nA;  wOn[p] = p0 ? nA : nS;
    }
  }
  u64 urp[4], uzp[4], unp[4];
  {
    const float* Uf = Whh + f*24*8;
    #pragma unroll
    for (int p = 0; p < 4; ++p){
      urp[p] = pk(0.5f*Uf[(0 + j)*8 + 2*p], 0.5f*Uf[(0 + j)*8 + 2*p+1]);
      uzp[p] = pk(0.5f*Uf[(8 + j)*8 + 2*p], 0.5f*Uf[(8 + j)*8 + 2*p+1]);
      unp[p] = pk(0.5f*Uf[(16 + j)*8 + 2*p], 0.5f*Uf[(16 + j)*8 + 2*p+1]);
    }
  }
  const u64 brp  = pk(0.5f*(bih[f*24 + j]     + bhh[f*24 + j]),     0.f);
  const u64 bzp  = pk(0.5f*(bih[f*24 + 8 + j] + bhh[f*24 + 8 + j]), 0.f);
  const u64 bxnp = pk(bih[f*24 + 16 + j], 0.f);
  const u64 bhnp = pk(0.5f*bhh[f*24 + 16 + j], 0.f);
  const u64 Z64  = 0ULL;

  // ---- staging: R4-proven contiguous 16B cp.async (~30 LSU ops/step/SM)
  auto stage = [&](int c, int buf){
    #pragma unroll
    for (int blx = 0; blx < BPC; ++blx){
      const float* src = x + ((size_t)(bg0 + blx)*TSTEPS + (size_t)c*CHK)*XDIM;
      uint32_t dst = (uint32_t)__cvta_generic_to_shared(&xs[buf][blx][0]);
      for (int i = tid; i < (CHK*XDIM)/4; i += NTHREADS)
        cp16(dst + (uint32_t)i*16u, src + i*4);
    }
  };

  stage(0, 0); asm volatile("cp.async.commit_group;" ::: "memory");
  stage(1, 1); asm volatile("cp.async.commit_group;" ::: "memory");

  float h = 0.f;
  float* outp = out + (((size_t)(bg0 + bl)*TSTEPS)*NFEAT + f)*HDIM + j;

  auto run_chunk = [&](auto DPc, const float* chunk, float* outc){
    constexpr int DP = decltype(DPc)::value;
    // even-step base: startf - p0; odd-step base: startf + 59 - (1-p0)
    const double* xE = (const double*)(chunk + (startf - p0));
    const double* xO = (const double*)(chunk + (startf + 58 + p0));

    auto step = [&](const double* xp,
                    const u64 (&wr)[7], const u64 (&wz)[7], const u64 (&wn)[7],
                    float* oaddr){
      u64 gr = brp, gz = bzp, gn = bxnp;
      #pragma unroll
      for (int p = 0; p < DP; ++p){
        u64 X = asu(xp[p]);                 // LDS.64, 8B-aligned by construction
        gr = fma2(wr[p], X, gr);
        gz = fma2(wz[p], X, gz);
        gn = fma2(wn[p], X, gn);
      }
      float hk0 = __shfl_sync(0xFFFFFFFFu, h, 0, 8);
      float hk1 = __shfl_sync(0xFFFFFFFFu, h, 1, 8);
      float hk2 = __shfl_sync(0xFFFFFFFFu, h, 2, 8);
      float hk3 = __shfl_sync(0xFFFFFFFFu, h, 3, 8);
      float hk4 = __shfl_sync(0xFFFFFFFFu, h, 4, 8);
      float hk5 = __shfl_sync(0xFFFFFFFFu, h, 5, 8);
      float hk6 = __shfl_sync(0xFFFFFFFFu, h, 6, 8);
      float hk7 = __shfl_sync(0xFFFFFFFFu, h, 7, 8);
      u64 H01 = pk(hk0,hk1), H23 = pk(hk2,hk3), H45 = pk(hk4,hk5), H67 = pk(hk6,hk7);

      u64 rA = fma2(urp[0], H01, gr); rA = fma2(urp[1], H23, rA);
      u64 rB = fma2(urp[2], H45, Z64); rB = fma2(urp[3], H67, rB);
      float tr = tanh_ap(hsum(add2(rA, rB)));

      u64 zA = fma2(uzp[0], H01, gz); zA = fma2(uzp[1], H23, zA);
      u64 zB = fma2(uzp[2], H45, Z64); zB = fma2(uzp[3], H67, zB);
      float tz = tanh_ap(hsum(add2(zA, zB)));

      u64 nA = fma2(unp[0], H01, bhnp); nA = fma2(unp[1], H23, nA);
      u64 nB = fma2(unp[2], H45, Z64);  nB = fma2(unp[3], H67, nB);
      u64 nacc = add2(nA, nB);
      float hnh = hsum(nacc);                 // 0.5*(Un h + bhn)
      float s   = hsum(gn) + hnh;             // gn + hnh
      float a   = fmaf(tr, hnh, s);           // gn + r*(Un h + bhn)
      float n   = tanh_ap(a);
      float uu  = 0.5f*(h - n);
      h = fmaf(tz, uu, n + uu);               // (1-z)*n + z*h
      if (wen) *oaddr = h;
    };

    #pragma unroll 2
    for (int t2 = 0; t2 < CHK/2; ++t2){
      step(xE + t2*(XDIM), wEr, wEz, wEn, outc + (size_t)(2*t2)*(NFEAT*HDIM));
      step(xO + t2*(XDIM), wOr, wOz, wOn, outc + (size_t)(2*t2+1)*(NFEAT*HDIM));
    }
  };

  for (int c = 0; c < NCHK; ++c){
    asm volatile("cp.async.wait_group 1;" ::: "memory");
    __syncthreads();
    const float* chunk = &xs[c & 1][bl][0];
    float* outc = outp + (size_t)c*CHK*(NFEAT*HDIM);

    if (dp == 7)      run_chunk(IC<7>{}, chunk, outc);
    else if (dp == 2) run_chunk(IC<2>{}, chunk, outc);
    else              run_chunk(IC<1>{}, chunk, outc);

    __syncthreads();                          // buffer free before restage
    if (c + 2 < NCHK) stage(c + 2, c & 1);
    asm volatile("cp.async.commit_group;" ::: "memory");
  }
}

extern "C" void kernel_launch(void* const* d_in, const int* in_sizes, int n_in,
                              void* d_out, int out_size)
{
  const float* x   = (const float*)d_in[0];
  const float* Wih = (const float*)d_in[1];
  const float* Whh = (const float*)d_in[2];
  const float* bih = (const float*)d_in[3];
  const float* bhh = (const float*)d_in[4];
  (void)in_sizes; (void)n_in; (void)out_size;
  mcgru_kernel<<<BSZ/BPC, NTHREADS>>>(x, Wih, Whh, bih, bhh, (float*)d_out);
}